// round 4
// baseline (speedup 1.0000x reference)
#include <cuda_runtime.h>
#include <cuda_bf16.h>
#include <float.h>

// Problem constants
#define BB 2
#define HH 16
#define SS 2048
#define DD 128
#define BM 64
#define BN 64
#define NTHREADS 256
#define NTILES (SS / BM)

// Shared memory: Qs/Ks/Vs as float4[64][32] (XOR swizzled), Ps as float[64][68]
#define SMEM_BYTES (3 * 64 * 32 * 16 + 64 * 68 * 4)

__global__ __launch_bounds__(NTHREADS, 1)
void attn_flash_fp32_kernel(const float* __restrict__ Q,
                            const float* __restrict__ K,
                            const float* __restrict__ V,
                            const float* __restrict__ AM,   // [B,1,1,S] additive
                            const float* __restrict__ HM,   // [1,H,1,1] multiplicative
                            const float* __restrict__ CTX,  // [B,S]     post-softmax
                            float* __restrict__ out)
{
    extern __shared__ char smem_raw[];
    float4* Qs = reinterpret_cast<float4*>(smem_raw);
    float4* Ks = Qs + 64 * 32;
    float4* Vs = Ks + 64 * 32;
    float*  Ps = reinterpret_cast<float*>(Vs + 64 * 32);

    const int tid = threadIdx.x;
    const int ty  = tid >> 4;   // 0..15 : query-group
    const int tx  = tid & 15;   // 0..15 : key-group / dim-group

    // Reverse so the heaviest CTAs (largest causal extent) launch first.
    const int it = (gridDim.x - 1) - blockIdx.x;
    const int h  = blockIdx.y;
    const int b  = blockIdx.z;
    const int q0 = it * BM;

    const float* Qp = Q + (((size_t)b * HH + h) * SS + q0) * DD;
    const float* Kb = K + (((size_t)b * HH + h) * SS) * DD;
    const float* Vb = V + (((size_t)b * HH + h) * SS) * DD;

    // ---- Load Q tile, swizzled: phys g = g ^ (row & 7) ----
    #pragma unroll
    for (int r = 0; r < 8; ++r) {
        int flat = tid + r * NTHREADS;      // 0..2047
        int row  = flat >> 5;               // 0..63
        int g    = flat & 31;               // 0..31
        Qs[row * 32 + (g ^ (row & 7))] = ((const float4*)Qp)[row * 32 + g];
    }

    // O fragment: 4 query rows x (2 x float4) dims.  dims: [4*tx..4*tx+3] and [64+4*tx..64+4*tx+3]
    float o[4][2][4];
    #pragma unroll
    for (int i = 0; i < 4; ++i)
        #pragma unroll
        for (int e = 0; e < 2; ++e)
            #pragma unroll
            for (int c = 0; c < 4; ++c) o[i][e][c] = 0.f;

    float mrun[4], zrun[4];
    #pragma unroll
    for (int i = 0; i < 4; ++i) { mrun[i] = -FLT_MAX; zrun[i] = 0.f; }

    for (int jt = 0; jt <= it; ++jt) {
        const int kbase = jt * BN;

        __syncthreads();  // protect Ks/Vs/Ps reuse from previous iteration

        // ---- Load K and V tiles (swizzled) ----
        const float4* Kg = (const float4*)(Kb + (size_t)kbase * DD);
        const float4* Vg = (const float4*)(Vb + (size_t)kbase * DD);
        #pragma unroll
        for (int r = 0; r < 8; ++r) {
            int flat = tid + r * NTHREADS;
            int row  = flat >> 5;
            int g    = flat & 31;
            int sidx = row * 32 + (g ^ (row & 7));
            Ks[sidx] = Kg[row * 32 + g];
            Vs[sidx] = Vg[row * 32 + g];
        }

        float amv[4], cxv[4];
        #pragma unroll
        for (int j = 0; j < 4; ++j) {
            int kg = kbase + tx + 16 * j;
            amv[j] = AM[(size_t)b * SS + kg];
            cxv[j] = CTX[(size_t)b * SS + kg];
        }
        __syncthreads();

        // ---- S = Q K^T  (4x4 fragment per thread) ----
        float acc[4][4];
        #pragma unroll
        for (int i = 0; i < 4; ++i)
            #pragma unroll
            for (int j = 0; j < 4; ++j) acc[i][j] = 0.f;

        const int swq = ty & 7;
        const int swk = tx & 7;
        #pragma unroll 8
        for (int g = 0; g < 32; ++g) {
            float4 qf[4], kf[4];
            int gq = g ^ swq;
            int gk = g ^ swk;
            #pragma unroll
            for (int i = 0; i < 4; ++i) qf[i] = Qs[(ty + 16 * i) * 32 + gq];
            #pragma unroll
            for (int j = 0; j < 4; ++j) kf[j] = Ks[(tx + 16 * j) * 32 + gk];
            #pragma unroll
            for (int i = 0; i < 4; ++i)
                #pragma unroll
                for (int j = 0; j < 4; ++j) {
                    acc[i][j] += qf[i].x * kf[j].x;
                    acc[i][j] += qf[i].y * kf[j].y;
                    acc[i][j] += qf[i].z * kf[j].z;
                    acc[i][j] += qf[i].w * kf[j].w;
                }
        }

        // ---- Masks + online softmax ----
        const bool diag = (jt == it);
        #pragma unroll
        for (int i = 0; i < 4; ++i) {
            const int qg = q0 + ty + 16 * i;
            float l[4];
            #pragma unroll
            for (int j = 0; j < 4; ++j) {
                int kg = kbase + tx + 16 * j;
                float v = acc[i][j];
                if (diag && kg > qg) v = -3.402823466e38f;  // finfo(f32).min
                l[j] = v + amv[j];                           // additive mask AFTER causal
            }
            float mt = fmaxf(fmaxf(l[0], l[1]), fmaxf(l[2], l[3]));
            #pragma unroll
            for (int off = 8; off > 0; off >>= 1)
                mt = fmaxf(mt, __shfl_xor_sync(0xffffffffu, mt, off));
            float mnew  = fmaxf(mrun[i], mt);
            float alpha = __expf(mrun[i] - mnew);
            mrun[i] = mnew;

            float zl = 0.f;
            #pragma unroll
            for (int j = 0; j < 4; ++j) {
                float p = __expf(l[j] - mnew);
                zl += p;                                        // Z uses UNSCALED p
                Ps[(ty + 16 * i) * 68 + tx + 16 * j] = p * cxv[j];  // ctx applied post-softmax
            }
            #pragma unroll
            for (int off = 8; off > 0; off >>= 1)
                zl += __shfl_xor_sync(0xffffffffu, zl, off);
            zrun[i] = zrun[i] * alpha + zl;

            #pragma unroll
            for (int e = 0; e < 2; ++e)
                #pragma unroll
                for (int c = 0; c < 4; ++c) o[i][e][c] *= alpha;
        }
        __syncthreads();

        // ---- O += P V  (4 rows x 8 dims per thread) ----
        #pragma unroll 4
        for (int k4 = 0; k4 < 16; ++k4) {
            float4 pf[4];
            #pragma unroll
            for (int i = 0; i < 4; ++i)
                pf[i] = *(const float4*)&Ps[(ty + 16 * i) * 68 + k4 * 4];
            #pragma unroll
            for (int kk = 0; kk < 4; ++kk) {
                int k  = k4 * 4 + kk;
                int sw = k & 7;
                float4 v0 = Vs[k * 32 + (tx ^ sw)];
                float4 v1 = Vs[k * 32 + ((tx + 16) ^ sw)];
                #pragma unroll
                for (int i = 0; i < 4; ++i) {
                    float p = (kk == 0) ? pf[i].x : (kk == 1) ? pf[i].y
                            : (kk == 2) ? pf[i].z : pf[i].w;
                    o[i][0][0] += p * v0.x; o[i][0][1] += p * v0.y;
                    o[i][0][2] += p * v0.z; o[i][0][3] += p * v0.w;
                    o[i][1][0] += p * v1.x; o[i][1][1] += p * v1.y;
                    o[i][1][2] += p * v1.z; o[i][1][3] += p * v1.w;
                }
            }
        }
    }

    // ---- Epilogue: /Z, * head_mask, store ----
    const float hm = HM[h];
    float* Op = out + (((size_t)b * HH + h) * SS + q0) * DD;
    #pragma unroll
    for (int i = 0; i < 4; ++i) {
        float inv = hm / zrun[i];
        int row = ty + 16 * i;
        #pragma unroll
        for (int e = 0; e < 2; ++e) {
            float4 v;
            v.x = o[i][e][0] * inv;
            v.y = o[i][e][1] * inv;
            v.z = o[i][e][2] * inv;
            v.w = o[i][e][3] * inv;
            ((float4*)(Op + (size_t)row * DD))[tx + 16 * e] = v;
        }
    }
}

extern "C" void kernel_launch(void* const* d_in, const int* in_sizes, int n_in,
                              void* d_out, int out_size)
{
    (void)in_sizes; (void)n_in; (void)out_size;
    const float* Q   = (const float*)d_in[0];
    const float* K   = (const float*)d_in[1];
    const float* V   = (const float*)d_in[2];
    const float* AM  = (const float*)d_in[3];
    const float* HM  = (const float*)d_in[4];
    const float* CTX = (const float*)d_in[5];
    float* out = (float*)d_out;

    cudaFuncSetAttribute(attn_flash_fp32_kernel,
                         cudaFuncAttributeMaxDynamicSharedMemorySize, SMEM_BYTES);

    dim3 grid(NTILES, HH, BB);
    attn_flash_fp32_kernel<<<grid, NTHREADS, SMEM_BYTES>>>(Q, K, V, AM, HM, CTX, out);
}

// round 6
// speedup vs baseline: 1.9400x; 1.9400x over previous
#include <cuda_runtime.h>
#include <cuda_bf16.h>
#include <cstdint>

#define HH 16
#define SS 2048
#define DD 128
#define BM 128
#define BN 64
#define NT 256

// ---- smem layout (bytes) ----
#define OFF_AM  0                     // 64 floats
#define OFF_CX  256                   // 64 floats
#define OFF_QHI 1024                  // 128 rows x 256B
#define OFF_QLO (OFF_QHI + 32768)
#define OFF_KHI (OFF_QLO + 32768)     // 64 rows x 256B
#define OFF_KLO (OFF_KHI + 16384)
#define OFF_VHI (OFF_KLO + 16384)     // VT: 128 rows x 128B
#define OFF_VLO (OFF_VHI + 16384)
#define SMEM_TOTAL (OFF_VLO + 16384)  // 132096

__device__ __forceinline__ uint32_t smem_u32(const void* p){
    uint32_t a;
    asm("{ .reg .u64 t; cvta.to.shared.u64 t, %1; cvt.u32.u64 %0, t; }" : "=r"(a) : "l"(p));
    return a;
}
__device__ __forceinline__ void split2(float x, float y, uint32_t& hi, uint32_t& lo){
    __nv_bfloat162 h = __floats2bfloat162_rn(x, y);
    __nv_bfloat162 l = __floats2bfloat162_rn(x - __bfloat162float(h.x), y - __bfloat162float(h.y));
    hi = *reinterpret_cast<uint32_t*>(&h);
    lo = *reinterpret_cast<uint32_t*>(&l);
}
__device__ __forceinline__ void mma_bf16(float* d, const uint32_t* a, uint32_t b0, uint32_t b1){
    asm volatile(
        "mma.sync.aligned.m16n8k16.row.col.f32.bf16.bf16.f32 "
        "{%0,%1,%2,%3}, {%4,%5,%6,%7}, {%8,%9}, {%0,%1,%2,%3};"
        : "+f"(d[0]), "+f"(d[1]), "+f"(d[2]), "+f"(d[3])
        : "r"(a[0]), "r"(a[1]), "r"(a[2]), "r"(a[3]), "r"(b0), "r"(b1));
}
__device__ __forceinline__ void ldsm4(uint32_t* r, uint32_t addr){
    asm volatile("ldmatrix.sync.aligned.m8n8.x4.shared.b16 {%0,%1,%2,%3}, [%4];"
        : "=r"(r[0]), "=r"(r[1]), "=r"(r[2]), "=r"(r[3]) : "r"(addr));
}

__global__ __launch_bounds__(NT, 1)
void attn_hmma_kernel(const float* __restrict__ Q, const float* __restrict__ K,
                      const float* __restrict__ V, const float* __restrict__ AM,
                      const float* __restrict__ HM, const float* __restrict__ CTX,
                      float* __restrict__ out)
{
    extern __shared__ char sm[];
    const uint32_t sb = smem_u32(sm);
    const int tid = threadIdx.x, wid = tid >> 5, lane = tid & 31;

    const int it = (gridDim.x - 1) - blockIdx.x;  // heavy q-tiles first
    const int h = blockIdx.y, b = blockIdx.z;
    const int q0 = it * BM;
    const int nt = 2 * (it + 1);                  // 64-key tiles to process

    const float* Qp = Q + (((size_t)b * HH + h) * SS + q0) * DD;
    const float* Kb = K + (((size_t)b * HH + h) * SS) * DD;
    const float* Vb = V + (((size_t)b * HH + h) * SS) * DD;
    const size_t bS = (size_t)b * SS;

    // ---- prologue: Q split hi/lo into swizzled smem (256B rows, 16B-chunk XOR) ----
    {
        const float4* Qg = (const float4*)Qp;
        for (int flat = tid; flat < BM * 32; flat += NT){
            int r = flat >> 5, g = flat & 31;
            float4 v = Qg[flat];
            uint32_t h0, l0, h1, l1;
            split2(v.x, v.y, h0, l0);
            split2(v.z, v.w, h1, l1);
            uint32_t o = (uint32_t)r * 256u
                       + ((((uint32_t)(g >> 1)) ^ ((uint32_t)r & 7u)) << 4)
                       + (((uint32_t)(g & 1)) << 3);
            *(uint2*)(sm + OFF_QHI + o) = make_uint2(h0, h1);
            *(uint2*)(sm + OFF_QLO + o) = make_uint2(l0, l1);
        }
    }

    // ---- per-lane fragment addressing ----
    const int rowA = 16 * wid + (lane & 15);         // A-frag row (lanes 0-15 / 16-31 = chunk halves)
    const uint32_t qbh = sb + OFF_QHI + rowA * 256;
    const uint32_t qbl = sb + OFF_QLO + rowA * 256;
    const uint32_t swA = rowA & 7, hi4 = lane >> 4;
    const int rB  = (lane & 7) + ((lane >> 4) & 1) * 8;  // B-frag row pattern
    const uint32_t cof = (lane >> 3) & 1;                // B-frag chunk half

    const int g    = lane >> 2;                       // accum row within 8
    const int colt = 2 * (lane & 3);                  // accum col pair
    const int qg0 = q0 + 16 * wid + g;
    const int qg1 = qg0 + 8;

    float oacc[16][4];
    #pragma unroll
    for (int i = 0; i < 16; ++i)
        #pragma unroll
        for (int j = 0; j < 4; ++j) oacc[i][j] = 0.f;
    float z0t = 0.f, z1t = 0.f;

    for (int jt = 0; jt < nt; ++jt){
        const int kbase = jt * BN;
        __syncthreads();   // previous tile fully consumed

        // ---- load K tile [64,128] split -> smem ----
        const float4* Kg = (const float4*)(Kb + (size_t)kbase * DD);
        for (int flat = tid; flat < BN * 32; flat += NT){
            int r = flat >> 5, gg = flat & 31;
            float4 v = Kg[flat];
            uint32_t h0, l0, h1, l1;
            split2(v.x, v.y, h0, l0);
            split2(v.z, v.w, h1, l1);
            uint32_t o = (uint32_t)r * 256u
                       + ((((uint32_t)(gg >> 1)) ^ ((uint32_t)r & 7u)) << 4)
                       + (((uint32_t)(gg & 1)) << 3);
            *(uint2*)(sm + OFF_KHI + o) = make_uint2(h0, h1);
            *(uint2*)(sm + OFF_KLO + o) = make_uint2(l0, l1);
        }
        // ---- load V tile transposed: VT[dim][key], 128B rows ----
        for (int flat = tid; flat < 2048; flat += NT){
            int kg = flat >> 7, c = flat & 127;
            const float* vp = Vb + (size_t)(kbase + 4 * kg) * DD + c;
            float v0 = vp[0], v1 = vp[DD], v2 = vp[2 * DD], v3 = vp[3 * DD];
            uint32_t h0, l0, h1, l1;
            split2(v0, v1, h0, l0);
            split2(v2, v3, h1, l1);
            uint32_t o = (uint32_t)c * 128u
                       + ((((uint32_t)(kg >> 1)) ^ ((uint32_t)c & 7u)) << 4)
                       + (((uint32_t)(kg & 1)) << 3);
            *(uint2*)(sm + OFF_VHI + o) = make_uint2(h0, h1);
            *(uint2*)(sm + OFF_VLO + o) = make_uint2(l0, l1);
        }
        if (tid < 64)        ((float*)(sm + OFF_AM))[tid]      = AM[bS + kbase + tid];
        else if (tid < 128)  ((float*)(sm + OFF_CX))[tid - 64] = CTX[bS + kbase + (tid - 64)];
        __syncthreads();

        // ---- S = Q K^T : 3-way bf16 split, 192 HMMA/warp ----
        float sacc[8][4];
        #pragma unroll
        for (int i = 0; i < 8; ++i)
            #pragma unroll
            for (int j = 0; j < 4; ++j) sacc[i][j] = 0.f;

        #pragma unroll
        for (int kb = 0; kb < 8; ++kb){
            uint32_t ah[4], al[4];
            uint32_t coff = (((uint32_t)(2 * kb) + hi4) ^ swA) << 4;
            ldsm4(ah, qbh + coff);
            ldsm4(al, qbl + coff);
            #pragma unroll
            for (int np = 0; np < 4; ++np){
                int rowB = 16 * np + rB;
                uint32_t ko = (uint32_t)rowB * 256u
                            + ((((uint32_t)(2 * kb) + cof) ^ ((uint32_t)rowB & 7u)) << 4);
                uint32_t bh[4], bl[4];
                ldsm4(bh, sb + OFF_KHI + ko);
                ldsm4(bl, sb + OFF_KLO + ko);
                mma_bf16(sacc[2 * np],     ah, bh[0], bh[1]);
                mma_bf16(sacc[2 * np + 1], ah, bh[2], bh[3]);
                mma_bf16(sacc[2 * np],     ah, bl[0], bl[1]);
                mma_bf16(sacc[2 * np + 1], ah, bl[2], bl[3]);
                mma_bf16(sacc[2 * np],     al, bh[0], bh[1]);
                mma_bf16(sacc[2 * np + 1], al, bh[2], bh[3]);
            }
        }

        // ---- softmax (m=0): p = exp(s+am) with causal zeroing; P -> bf16 hi/lo frags ----
        uint32_t PH[8][2], PL[8][2];
        const float* amb = (const float*)(sm + OFF_AM);
        const float* cxb = (const float*)(sm + OFF_CX);
        float z0 = 0.f, z1 = 0.f;
        #pragma unroll
        for (int j = 0; j < 8; ++j){
            int col = kbase + 8 * j + colt;
            float2 am2 = *(const float2*)&amb[8 * j + colt];
            float2 cx2 = *(const float2*)&cxb[8 * j + colt];
            float p0 = (col     <= qg0) ? __expf(sacc[j][0] + am2.x) : 0.f;
            float p1 = (col + 1 <= qg0) ? __expf(sacc[j][1] + am2.y) : 0.f;
            float p2 = (col     <= qg1) ? __expf(sacc[j][2] + am2.x) : 0.f;
            float p3 = (col + 1 <= qg1) ? __expf(sacc[j][3] + am2.y) : 0.f;
            z0 += p0 + p1;  z1 += p2 + p3;        // Z uses UNSCALED p
            p0 *= cx2.x; p1 *= cx2.y;             // ctx applied post-softmax
            p2 *= cx2.x; p3 *= cx2.y;
            split2(p0, p1, PH[j][0], PL[j][0]);
            split2(p2, p3, PH[j][1], PL[j][1]);
        }
        z0 += __shfl_xor_sync(0xffffffffu, z0, 1);
        z0 += __shfl_xor_sync(0xffffffffu, z0, 2);
        z1 += __shfl_xor_sync(0xffffffffu, z1, 1);
        z1 += __shfl_xor_sync(0xffffffffu, z1, 2);
        z0t += z0;  z1t += z1;

        // ---- O += P V : P frags straight from registers, 192 HMMA/warp ----
        #pragma unroll
        for (int kb = 0; kb < 4; ++kb){
            uint32_t Ahf[4] = {PH[2 * kb][0], PH[2 * kb][1], PH[2 * kb + 1][0], PH[2 * kb + 1][1]};
            uint32_t Alf[4] = {PL[2 * kb][0], PL[2 * kb][1], PL[2 * kb + 1][0], PL[2 * kb + 1][1]};
            #pragma unroll
            for (int np = 0; np < 8; ++np){
                int rowV = 16 * np + rB;
                uint32_t vo = (uint32_t)rowV * 128u
                            + ((((uint32_t)(2 * kb) + cof) ^ ((uint32_t)rowV & 7u)) << 4);
                uint32_t vh[4], vl[4];
                ldsm4(vh, sb + OFF_VHI + vo);
                ldsm4(vl, sb + OFF_VLO + vo);
                mma_bf16(oacc[2 * np],     Ahf, vh[0], vh[1]);
                mma_bf16(oacc[2 * np + 1], Ahf, vh[2], vh[3]);
                mma_bf16(oacc[2 * np],     Ahf, vl[0], vl[1]);
                mma_bf16(oacc[2 * np + 1], Ahf, vl[2], vl[3]);
                mma_bf16(oacc[2 * np],     Alf, vh[0], vh[1]);
                mma_bf16(oacc[2 * np + 1], Alf, vh[2], vh[3]);
            }
        }
    }

    // ---- epilogue: /Z, * head_mask, store ----
    const float hm = HM[h];
    const float i0 = hm / z0t, i1 = hm / z1t;
    float* O0 = out + (((size_t)b * HH + h) * SS + q0 + 16 * wid + g) * DD;
    float* O1 = O0 + 8 * DD;
    #pragma unroll
    for (int nb = 0; nb < 16; ++nb){
        *(float2*)&O0[8 * nb + colt] = make_float2(oacc[nb][0] * i0, oacc[nb][1] * i0);
        *(float2*)&O1[8 * nb + colt] = make_float2(oacc[nb][2] * i1, oacc[nb][3] * i1);
    }
}

extern "C" void kernel_launch(void* const* d_in, const int* in_sizes, int n_in,
                              void* d_out, int out_size)
{
    (void)in_sizes; (void)n_in; (void)out_size;
    const float* Q   = (const float*)d_in[0];
    const float* K   = (const float*)d_in[1];
    const float* V   = (const float*)d_in[2];
    const float* AM  = (const float*)d_in[3];
    const float* HM  = (const float*)d_in[4];
    const float* CTX = (const float*)d_in[5];
    float* out = (float*)d_out;

    cudaFuncSetAttribute(attn_hmma_kernel,
                         cudaFuncAttributeMaxDynamicSharedMemorySize, SMEM_TOTAL);

    dim3 grid(SS / BM, HH, 2);
    attn_hmma_kernel<<<grid, NT, SMEM_TOTAL>>>(Q, K, V, AM, HM, CTX, out);
}

// round 8
// speedup vs baseline: 2.5435x; 1.3111x over previous
#include <cuda_runtime.h>
#include <cuda_bf16.h>
#include <cstdint>

#define HH 16
#define SS 2048
#define DD 128
#define BM 128
#define BN 64
#define NT 256

// ---- smem layout (bytes) ----
#define OFF_AMCX 0                    // 2 bufs x (am 256B + cx 256B)
#define OFF_QHI  1024                 // 128 rows x 256B
#define OFF_QLO  33792
#define OFF_KHI  66560                // 64 rows x 256B
#define OFF_KLO  82944
#define OFF_VHI  99328                // VT: 128 rows x 128B
#define OFF_VLO  115712
#define OFF_RAWK 132096               // 64 x 128 fp32
#define OFF_RAWV 164864               // 64 x 132 fp32 (pad 4)
#define SMEM_TOTAL 198656

__device__ __forceinline__ uint32_t smem_u32(const void* p){
    uint32_t a;
    asm("{ .reg .u64 t; cvta.to.shared.u64 t, %1; cvt.u32.u64 %0, t; }" : "=r"(a) : "l"(p));
    return a;
}
__device__ __forceinline__ void split2(float x, float y, uint32_t& hi, uint32_t& lo){
    __nv_bfloat162 h = __floats2bfloat162_rn(x, y);
    __nv_bfloat162 l = __floats2bfloat162_rn(x - __bfloat162float(h.x), y - __bfloat162float(h.y));
    hi = *reinterpret_cast<uint32_t*>(&h);
    lo = *reinterpret_cast<uint32_t*>(&l);
}
// NOTE: non-volatile on purpose — pure register function, lets ptxas schedule.
__device__ __forceinline__ void mma_bf16(float* d, const uint32_t* a, uint32_t b0, uint32_t b1){
    asm("mma.sync.aligned.m16n8k16.row.col.f32.bf16.bf16.f32 "
        "{%0,%1,%2,%3}, {%4,%5,%6,%7}, {%8,%9}, {%0,%1,%2,%3};"
        : "+f"(d[0]), "+f"(d[1]), "+f"(d[2]), "+f"(d[3])
        : "r"(a[0]), "r"(a[1]), "r"(a[2]), "r"(a[3]), "r"(b0), "r"(b1));
}
__device__ __forceinline__ void ldsm4(uint32_t* r, uint32_t addr){
    asm("ldmatrix.sync.aligned.m8n8.x4.shared.b16 {%0,%1,%2,%3}, [%4];"
        : "=r"(r[0]), "=r"(r[1]), "=r"(r[2]), "=r"(r[3]) : "r"(addr) : "memory");
}
__device__ __forceinline__ void cpa16(uint32_t dst, const void* src){
    asm volatile("cp.async.cg.shared.global [%0], [%1], 16;" :: "r"(dst), "l"(src));
}
__device__ __forceinline__ void cpa8(uint32_t dst, const void* src){
    asm volatile("cp.async.ca.shared.global [%0], [%1], 8;" :: "r"(dst), "l"(src));
}
#define CP_COMMIT() asm volatile("cp.async.commit_group;" ::: "memory")
#define CP_WAIT0()  asm volatile("cp.async.wait_group 0;" ::: "memory")

// Stream raw fp32 K/V tile (+am/ctx) into smem staging via cp.async.
__device__ __forceinline__ void issue_loads(const float* Kb, const float* Vb,
                                            const float* AM, const float* CTX,
                                            size_t bS, int kbase, int buf,
                                            uint32_t sb, int tid)
{
    const float4* Kg = (const float4*)(Kb + (size_t)kbase * DD);
    #pragma unroll
    for (int i = 0; i < 8; ++i){
        int flat = tid + i * NT;                 // 0..2047
        cpa16(sb + OFF_RAWK + flat * 16, Kg + flat);
    }
    const float4* Vg = (const float4*)(Vb + (size_t)kbase * DD);
    #pragma unroll
    for (int i = 0; i < 8; ++i){
        int flat = tid + i * NT;
        int r = flat >> 5, c4 = flat & 31;       // key row, float4 col
        cpa16(sb + OFF_RAWV + r * 528 + c4 * 16, Vg + flat);
    }
    // FIX (R7 bug): 64 floats each => 32 threads x 8B for AM, 32 for CTX.
    if (tid < 32)       cpa8(sb + OFF_AMCX + buf * 512 + tid * 8,              AM  + bS + kbase + 2 * tid);
    else if (tid < 64)  cpa8(sb + OFF_AMCX + buf * 512 + 256 + (tid - 32) * 8, CTX + bS + kbase + 2 * (tid - 32));
    CP_COMMIT();
}

// smem fp32 staging -> split bf16 hi/lo tiles (K row-major swizzled, V transposed swizzled)
__device__ __forceinline__ void split_tiles(char* sm, int tid)
{
    const float4* rk = (const float4*)(sm + OFF_RAWK);
    #pragma unroll
    for (int i = 0; i < 8; ++i){
        int flat = tid + i * NT;
        int r = flat >> 5, g = flat & 31;
        float4 v = rk[flat];
        uint32_t h0, l0, h1, l1;
        split2(v.x, v.y, h0, l0);
        split2(v.z, v.w, h1, l1);
        uint32_t o = (uint32_t)r * 256u
                   + ((((uint32_t)(g >> 1)) ^ ((uint32_t)r & 7u)) << 4)
                   + (((uint32_t)(g & 1)) << 3);
        *(uint2*)(sm + OFF_KHI + o) = make_uint2(h0, h1);
        *(uint2*)(sm + OFF_KLO + o) = make_uint2(l0, l1);
    }
    const float* rv = (const float*)(sm + OFF_RAWV);
    #pragma unroll
    for (int i = 0; i < 8; ++i){
        int flat = tid + i * NT;
        int kg = flat >> 7, c = flat & 127;
        const float* vp = rv + (size_t)(4 * kg) * 132 + c;
        float v0 = vp[0], v1 = vp[132], v2 = vp[264], v3 = vp[396];
        uint32_t h0, l0, h1, l1;
        split2(v0, v1, h0, l0);
        split2(v2, v3, h1, l1);
        uint32_t o = (uint32_t)c * 128u
                   + ((((uint32_t)(kg >> 1)) ^ ((uint32_t)c & 7u)) << 4)
                   + (((uint32_t)(kg & 1)) << 3);
        *(uint2*)(sm + OFF_VHI + o) = make_uint2(h0, h1);
        *(uint2*)(sm + OFF_VLO + o) = make_uint2(l0, l1);
    }
}

__global__ __launch_bounds__(NT, 1)
void attn_hmma_kernel(const float* __restrict__ Q, const float* __restrict__ K,
                      const float* __restrict__ V, const float* __restrict__ AM,
                      const float* __restrict__ HM, const float* __restrict__ CTX,
                      float* __restrict__ out)
{
    extern __shared__ char sm[];
    const uint32_t sb = smem_u32(sm);
    const int tid = threadIdx.x, wid = tid >> 5, lane = tid & 31;

    const int it = (gridDim.x - 1) - blockIdx.x;   // heavy q-tiles first
    const int h = blockIdx.y, b = blockIdx.z;
    const int q0 = it * BM;
    const int nt = 2 * (it + 1);

    const float* Qp = Q + (((size_t)b * HH + h) * SS + q0) * DD;
    const float* Kb = K + (((size_t)b * HH + h) * SS) * DD;
    const float* Vb = V + (((size_t)b * HH + h) * SS) * DD;
    const size_t bS = (size_t)b * SS;

    // ---- prologue: start tile-0 streaming, overlap with Q load+split ----
    issue_loads(Kb, Vb, AM, CTX, bS, 0, 0, sb, tid);
    {
        const float4* Qg = (const float4*)Qp;
        #pragma unroll
        for (int i = 0; i < 16; ++i){
            int flat = tid + i * NT;               // 0..4095
            int r = flat >> 5, g = flat & 31;
            float4 v = Qg[flat];
            uint32_t h0, l0, h1, l1;
            split2(v.x, v.y, h0, l0);
            split2(v.z, v.w, h1, l1);
            uint32_t o = (uint32_t)r * 256u
                       + ((((uint32_t)(g >> 1)) ^ ((uint32_t)r & 7u)) << 4)
                       + (((uint32_t)(g & 1)) << 3);
            *(uint2*)(sm + OFF_QHI + o) = make_uint2(h0, h1);
            *(uint2*)(sm + OFF_QLO + o) = make_uint2(l0, l1);
        }
    }
    CP_WAIT0();
    __syncthreads();
    split_tiles(sm, tid);
    __syncthreads();

    // ---- per-lane fragment addressing ----
    const int rowA = 16 * wid + (lane & 15);
    const uint32_t qbh = sb + OFF_QHI + rowA * 256;
    const uint32_t qbl = sb + OFF_QLO + rowA * 256;
    const uint32_t swA = rowA & 7, hi4 = lane >> 4;
    const int rB  = (lane & 7) + ((lane >> 4) & 1) * 8;
    const uint32_t cof = (lane >> 3) & 1;

    const int g    = lane >> 2;
    const int colt = 2 * (lane & 3);
    const int qg0 = q0 + 16 * wid + g;
    const int qg1 = qg0 + 8;

    float oacc[16][4];
    #pragma unroll
    for (int i = 0; i < 16; ++i)
        #pragma unroll
        for (int j = 0; j < 4; ++j) oacc[i][j] = 0.f;
    float z0t = 0.f, z1t = 0.f;

    for (int jt = 0; jt < nt; ++jt){
        const int kbase = jt * BN;
        const int cur = jt & 1;

        // stream next tile while we compute this one
        if (jt + 1 < nt)
            issue_loads(Kb, Vb, AM, CTX, bS, (jt + 1) * BN, (jt + 1) & 1, sb, tid);

        // ---- S = Q K^T : term-major sweeps over 8 independent accumulators ----
        float sacc[8][4];
        #pragma unroll
        for (int i = 0; i < 8; ++i)
            #pragma unroll
            for (int j = 0; j < 4; ++j) sacc[i][j] = 0.f;

        #pragma unroll
        for (int kb = 0; kb < 8; ++kb){
            uint32_t ah[4], al[4];
            uint32_t coff = (((uint32_t)(2 * kb) + hi4) ^ swA) << 4;
            ldsm4(ah, qbh + coff);
            ldsm4(al, qbl + coff);
            uint32_t bh[4][4], bl[4][4];
            #pragma unroll
            for (int np = 0; np < 4; ++np){
                int rowB = 16 * np + rB;
                uint32_t ko = (uint32_t)rowB * 256u
                            + ((((uint32_t)(2 * kb) + cof) ^ ((uint32_t)rowB & 7u)) << 4);
                ldsm4(bh[np], sb + OFF_KHI + ko);
                ldsm4(bl[np], sb + OFF_KLO + ko);
            }
            #pragma unroll
            for (int np = 0; np < 4; ++np){            // hi x hi
                mma_bf16(sacc[2 * np],     ah, bh[np][0], bh[np][1]);
                mma_bf16(sacc[2 * np + 1], ah, bh[np][2], bh[np][3]);
            }
            #pragma unroll
            for (int np = 0; np < 4; ++np){            // hi x lo
                mma_bf16(sacc[2 * np],     ah, bl[np][0], bl[np][1]);
                mma_bf16(sacc[2 * np + 1], ah, bl[np][2], bl[np][3]);
            }
            #pragma unroll
            for (int np = 0; np < 4; ++np){            // lo x hi
                mma_bf16(sacc[2 * np],     al, bh[np][0], bh[np][1]);
                mma_bf16(sacc[2 * np + 1], al, bh[np][2], bh[np][3]);
            }
        }

        // ---- softmax (m=0): p = exp(s+am), causal zeroing; P -> bf16 hi/lo frags ----
        uint32_t PH[8][2], PL[8][2];
        const float* amb = (const float*)(sm + OFF_AMCX + cur * 512);
        const float* cxb = amb + 64;
        float z0 = 0.f, z1 = 0.f;
        #pragma unroll
        for (int j = 0; j < 8; ++j){
            int col = kbase + 8 * j + colt;
            float2 am2 = *(const float2*)&amb[8 * j + colt];
            float2 cx2 = *(const float2*)&cxb[8 * j + colt];
            float p0 = (col     <= qg0) ? __expf(sacc[j][0] + am2.x) : 0.f;
            float p1 = (col + 1 <= qg0) ? __expf(sacc[j][1] + am2.y) : 0.f;
            float p2 = (col     <= qg1) ? __expf(sacc[j][2] + am2.x) : 0.f;
            float p3 = (col + 1 <= qg1) ? __expf(sacc[j][3] + am2.y) : 0.f;
            z0 += p0 + p1;  z1 += p2 + p3;        // Z uses UNSCALED p
            p0 *= cx2.x; p1 *= cx2.y;             // ctx applied post-softmax
            p2 *= cx2.x; p3 *= cx2.y;
            split2(p0, p1, PH[j][0], PL[j][0]);
            split2(p2, p3, PH[j][1], PL[j][1]);
        }
        z0 += __shfl_xor_sync(0xffffffffu, z0, 1);
        z0 += __shfl_xor_sync(0xffffffffu, z0, 2);
        z1 += __shfl_xor_sync(0xffffffffu, z1, 1);
        z1 += __shfl_xor_sync(0xffffffffu, z1, 2);
        z0t += z0;  z1t += z1;

        // ---- O += P V : P from registers, term-major sweeps over 8 accumulators ----
        #pragma unroll
        for (int kb = 0; kb < 4; ++kb){
            uint32_t Ahf[4] = {PH[2 * kb][0], PH[2 * kb][1], PH[2 * kb + 1][0], PH[2 * kb + 1][1]};
            uint32_t Alf[4] = {PL[2 * kb][0], PL[2 * kb][1], PL[2 * kb + 1][0], PL[2 * kb + 1][1]};
            #pragma unroll
            for (int hg = 0; hg < 2; ++hg){
                uint32_t vh[4][4], vl[4][4];
                #pragma unroll
                for (int q = 0; q < 4; ++q){
                    int rowV = 16 * (4 * hg + q) + rB;
                    uint32_t vo = (uint32_t)rowV * 128u
                                + ((((uint32_t)(2 * kb) + cof) ^ ((uint32_t)rowV & 7u)) << 4);
                    ldsm4(vh[q], sb + OFF_VHI + vo);
                    ldsm4(vl[q], sb + OFF_VLO + vo);
                }
                #pragma unroll
                for (int q = 0; q < 4; ++q){           // Ph x Vh
                    int np = 4 * hg + q;
                    mma_bf16(oacc[2 * np],     Ahf, vh[q][0], vh[q][1]);
                    mma_bf16(oacc[2 * np + 1], Ahf, vh[q][2], vh[q][3]);
                }
                #pragma unroll
                for (int q = 0; q < 4; ++q){           // Ph x Vl
                    int np = 4 * hg + q;
                    mma_bf16(oacc[2 * np],     Ahf, vl[q][0], vl[q][1]);
                    mma_bf16(oacc[2 * np + 1], Ahf, vl[q][2], vl[q][3]);
                }
                #pragma unroll
                for (int q = 0; q < 4; ++q){           // Pl x Vh
                    int np = 4 * hg + q;
                    mma_bf16(oacc[2 * np],     Alf, vh[q][0], vh[q][1]);
                    mma_bf16(oacc[2 * np + 1], Alf, vh[q][2], vh[q][3]);
                }
            }
        }

        // ---- make next tile's bf16 buffers ----
        if (jt + 1 < nt){
            CP_WAIT0();
            __syncthreads();        // all warps done reading current bf16 tiles
            split_tiles(sm, tid);
            __syncthreads();
        }
    }

    // ---- epilogue: /Z, * head_mask, store ----
    const float hm = HM[h];
    const float i0 = hm / z0t, i1 = hm / z1t;
    float* O0 = out + (((size_t)b * HH + h) * SS + q0 + 16 * wid + g) * DD;
    float* O1 = O0 + 8 * DD;
    #pragma unroll
    for (int nb = 0; nb < 16; ++nb){
        *(float2*)&O0[8 * nb + colt] = make_float2(oacc[nb][0] * i0, oacc[nb][1] * i0);
        *(float2*)&O1[8 * nb + colt] = make_float2(oacc[nb][2] * i1, oacc[nb][3] * i1);
    }
}

extern "C" void kernel_launch(void* const* d_in, const int* in_sizes, int n_in,
                              void* d_out, int out_size)
{
    (void)in_sizes; (void)n_in; (void)out_size;
    const float* Q   = (const float*)d_in[0];
    const float* K   = (const float*)d_in[1];
    const float* V   = (const float*)d_in[2];
    const float* AM  = (const float*)d_in[3];
    const float* HM  = (const float*)d_in[4];
    const float* CTX = (const float*)d_in[5];
    float* out = (float*)d_out;

    cudaFuncSetAttribute(attn_hmma_kernel,
                         cudaFuncAttributeMaxDynamicSharedMemorySize, SMEM_TOTAL);

    dim3 grid(SS / BM, HH, 2);
    attn_hmma_kernel<<<grid, NT, SMEM_TOTAL>>>(Q, K, V, AM, HM, CTX, out);
}

// round 9
// speedup vs baseline: 2.8224x; 1.1097x over previous
#include <cuda_runtime.h>
#include <cuda_bf16.h>
#include <cstdint>

#define HH 16
#define SS 2048
#define DD 128
#define BM 128
#define BN 64
#define NT 256
#define NELEM (2 * HH * SS * DD)     // 8388608 elements of K (and of V)

// ---- device scratch: split K and transposed-split V (bf16 hi/lo) ----
__device__ __nv_bfloat16 g_Khi[NELEM];
__device__ __nv_bfloat16 g_Klo[NELEM];
__device__ __nv_bfloat16 g_VThi[NELEM];   // [bh][d][s]
__device__ __nv_bfloat16 g_VTlo[NELEM];

// ---- main-kernel smem layout (bytes) ----
#define OFF_AMCX 0                     // 2 bufs x (am 256B + cx 256B)
#define OFF_QHI  1024                  // 128 rows x 256B
#define OFF_QLO  33792
#define OFF_KV   66560                 // 2 bufs x 64KB: [KHI 16K][KLO 16K][VHI 16K][VLO 16K]
#define SMEM_TOTAL 197632

__device__ __forceinline__ uint32_t smem_u32(const void* p){
    uint32_t a;
    asm("{ .reg .u64 t; cvta.to.shared.u64 t, %1; cvt.u32.u64 %0, t; }" : "=r"(a) : "l"(p));
    return a;
}
__device__ __forceinline__ void split2(float x, float y, uint32_t& hi, uint32_t& lo){
    __nv_bfloat162 h = __floats2bfloat162_rn(x, y);
    __nv_bfloat162 l = __floats2bfloat162_rn(x - __bfloat162float(h.x), y - __bfloat162float(h.y));
    hi = *reinterpret_cast<uint32_t*>(&h);
    lo = *reinterpret_cast<uint32_t*>(&l);
}
__device__ __forceinline__ void mma_bf16(float* d, const uint32_t* a, uint32_t b0, uint32_t b1){
    asm("mma.sync.aligned.m16n8k16.row.col.f32.bf16.bf16.f32 "
        "{%0,%1,%2,%3}, {%4,%5,%6,%7}, {%8,%9}, {%0,%1,%2,%3};"
        : "+f"(d[0]), "+f"(d[1]), "+f"(d[2]), "+f"(d[3])
        : "r"(a[0]), "r"(a[1]), "r"(a[2]), "r"(a[3]), "r"(b0), "r"(b1));
}
__device__ __forceinline__ void ldsm4(uint32_t* r, uint32_t addr){
    asm("ldmatrix.sync.aligned.m8n8.x4.shared.b16 {%0,%1,%2,%3}, [%4];"
        : "=r"(r[0]), "=r"(r[1]), "=r"(r[2]), "=r"(r[3]) : "r"(addr) : "memory");
}
__device__ __forceinline__ void cpa16(uint32_t dst, const void* src){
    asm volatile("cp.async.cg.shared.global [%0], [%1], 16;" :: "r"(dst), "l"(src));
}
__device__ __forceinline__ void cpa8(uint32_t dst, const void* src){
    asm volatile("cp.async.ca.shared.global [%0], [%1], 8;" :: "r"(dst), "l"(src));
}
#define CP_COMMIT() asm volatile("cp.async.commit_group;" ::: "memory")
#define CP_WAIT0()  asm volatile("cp.async.wait_group 0;" ::: "memory")
#define CP_WAIT1()  asm volatile("cp.async.wait_group 1;" ::: "memory")

// =================== prepass kernels ===================
// K: elementwise split, layout preserved (row-major [bh][s][d]).
__global__ void prep_k_kernel(const float* __restrict__ K){
    size_t i = (size_t)blockIdx.x * NT + threadIdx.x;   // float2 index
    float2 v = ((const float2*)K)[i];
    uint32_t h, l;
    split2(v.x, v.y, h, l);
    ((uint32_t*)g_Khi)[i] = h;
    ((uint32_t*)g_Klo)[i] = l;
}
// V: transpose per (b,h) to [d][s], then split.
__global__ void prep_v_kernel(const float* __restrict__ V){
    __shared__ float ts[32][33];
    const int bh = blockIdx.z, d0 = blockIdx.y * 32, s0 = blockIdx.x * 32;
    const int t = threadIdx.x, i = t >> 3, j4 = (t & 7) * 4;
    const float* Vp = V + ((size_t)bh * SS + s0) * DD + d0;
    float4 v = *(const float4*)(Vp + (size_t)i * DD + j4);
    ts[i][j4] = v.x; ts[i][j4 + 1] = v.y; ts[i][j4 + 2] = v.z; ts[i][j4 + 3] = v.w;
    __syncthreads();
    float a = ts[j4][i], b = ts[j4 + 1][i], c = ts[j4 + 2][i], d = ts[j4 + 3][i];
    uint32_t h0, l0, h1, l1;
    split2(a, b, h0, l0);
    split2(c, d, h1, l1);
    size_t dst = ((size_t)bh * DD + d0 + i) * SS + s0 + j4;
    *(uint2*)(g_VThi + dst) = make_uint2(h0, h1);
    *(uint2*)(g_VTlo + dst) = make_uint2(l0, l1);
}

// =================== main kernel ===================
// Stream pre-split bf16 K/V tile (+am/ctx) straight into swizzled smem.
__device__ __forceinline__ void issue_loads(const __nv_bfloat16* Khb, const __nv_bfloat16* Klb,
                                            const __nv_bfloat16* Vhb, const __nv_bfloat16* Vlb,
                                            const float* AM, const float* CTX, size_t bS,
                                            int kbase, int buf, uint32_t sb, int tid)
{
    const uint32_t kv = sb + OFF_KV + (uint32_t)buf * 65536u;
    #pragma unroll
    for (int i = 0; i < 4; ++i){                      // K: 64 rows x 16 chunks
        int flat = tid + i * NT;
        int r = flat >> 4, c = flat & 15;
        uint32_t o = (uint32_t)r * 256u + ((((uint32_t)c) ^ ((uint32_t)r & 7u)) << 4);
        const char* srcK = (const char*)(Khb + (size_t)(kbase + r) * DD) + c * 16;
        const char* srcL = (const char*)(Klb + (size_t)(kbase + r) * DD) + c * 16;
        cpa16(kv + o, srcK);
        cpa16(kv + 16384u + o, srcL);
    }
    #pragma unroll
    for (int i = 0; i < 4; ++i){                      // VT: 128 rows x 8 chunks
        int flat = tid + i * NT;
        int d = flat >> 3, c = flat & 7;
        uint32_t o = (uint32_t)d * 128u + ((((uint32_t)c) ^ ((uint32_t)d & 7u)) << 4);
        const char* srcH = (const char*)(Vhb + (size_t)d * SS + kbase) + c * 16;
        const char* srcL = (const char*)(Vlb + (size_t)d * SS + kbase) + c * 16;
        cpa16(kv + 32768u + o, srcH);
        cpa16(kv + 49152u + o, srcL);
    }
    if (tid < 32)       cpa8(sb + OFF_AMCX + buf * 512 + tid * 8,              AM  + bS + kbase + 2 * tid);
    else if (tid < 64)  cpa8(sb + OFF_AMCX + buf * 512 + 256 + (tid - 32) * 8, CTX + bS + kbase + 2 * (tid - 32));
    CP_COMMIT();
}

__global__ __launch_bounds__(NT, 1)
void attn_hmma_kernel(const float* __restrict__ Q,
                      const float* __restrict__ AM,
                      const float* __restrict__ HM,
                      const float* __restrict__ CTX,
                      float* __restrict__ out)
{
    extern __shared__ char sm[];
    const uint32_t sb = smem_u32(sm);
    const int tid = threadIdx.x, wid = tid >> 5, lane = tid & 31;

    const int it = (gridDim.x - 1) - blockIdx.x;   // heavy q-tiles first
    const int h = blockIdx.y, b = blockIdx.z;
    const int bh = b * HH + h;
    const int q0 = it * BM;
    const int nt = 2 * (it + 1);

    const float* Qp = Q + (((size_t)bh) * SS + q0) * DD;
    const __nv_bfloat16* Khb = g_Khi  + (size_t)bh * SS * DD;
    const __nv_bfloat16* Klb = g_Klo  + (size_t)bh * SS * DD;
    const __nv_bfloat16* Vhb = g_VThi + (size_t)bh * SS * DD;
    const __nv_bfloat16* Vlb = g_VTlo + (size_t)bh * SS * DD;
    const size_t bS = (size_t)b * SS;

    // ---- prologue: start tile-0 streaming, overlap with Q load+split ----
    issue_loads(Khb, Klb, Vhb, Vlb, AM, CTX, bS, 0, 0, sb, tid);
    {
        const float4* Qg = (const float4*)Qp;
        #pragma unroll
        for (int i = 0; i < 16; ++i){
            int flat = tid + i * NT;               // 0..4095
            int r = flat >> 5, g = flat & 31;
            float4 v = Qg[flat];
            uint32_t h0, l0, h1, l1;
            split2(v.x, v.y, h0, l0);
            split2(v.z, v.w, h1, l1);
            uint32_t o = (uint32_t)r * 256u
                       + ((((uint32_t)(g >> 1)) ^ ((uint32_t)r & 7u)) << 4)
                       + (((uint32_t)(g & 1)) << 3);
            *(uint2*)(sm + OFF_QHI + o) = make_uint2(h0, h1);
            *(uint2*)(sm + OFF_QLO + o) = make_uint2(l0, l1);
        }
    }

    // ---- per-lane fragment addressing ----
    const int rowA = 16 * wid + (lane & 15);
    const uint32_t qbh = sb + OFF_QHI + rowA * 256;
    const uint32_t qbl = sb + OFF_QLO + rowA * 256;
    const uint32_t swA = rowA & 7, hi4 = lane >> 4;
    const int rB  = (lane & 7) + ((lane >> 4) & 1) * 8;
    const uint32_t cof = (lane >> 3) & 1;

    const int g    = lane >> 2;
    const int colt = 2 * (lane & 3);
    const int qg0 = q0 + 16 * wid + g;
    const int qg1 = qg0 + 8;

    float oacc[16][4];
    #pragma unroll
    for (int i = 0; i < 16; ++i)
        #pragma unroll
        for (int j = 0; j < 4; ++j) oacc[i][j] = 0.f;
    float z0t = 0.f, z1t = 0.f;

    for (int jt = 0; jt < nt; ++jt){
        const int kbase = jt * BN;
        const int cur = jt & 1;
        const uint32_t kvb = sb + OFF_KV + (uint32_t)cur * 65536u;

        __syncthreads();      // all warps done reading buf cur^1 (tile jt-1)
        if (jt + 1 < nt){
            issue_loads(Khb, Klb, Vhb, Vlb, AM, CTX, bS, (jt + 1) * BN, cur ^ 1, sb, tid);
            CP_WAIT1();       // tile jt complete (jt+1 may stay in flight)
        } else {
            CP_WAIT0();
        }
        __syncthreads();      // tile jt visible to all threads

        // ---- S = Q K^T : term-major sweeps over 8 independent accumulators ----
        float sacc[8][4];
        #pragma unroll
        for (int i = 0; i < 8; ++i)
            #pragma unroll
            for (int j = 0; j < 4; ++j) sacc[i][j] = 0.f;

        #pragma unroll
        for (int kb = 0; kb < 8; ++kb){
            uint32_t ah[4], al[4];
            uint32_t coff = (((uint32_t)(2 * kb) + hi4) ^ swA) << 4;
            ldsm4(ah, qbh + coff);
            ldsm4(al, qbl + coff);
            uint32_t bh4[4][4], bl4[4][4];
            #pragma unroll
            for (int np = 0; np < 4; ++np){
                int rowB = 16 * np + rB;
                uint32_t ko = (uint32_t)rowB * 256u
                            + ((((uint32_t)(2 * kb) + cof) ^ ((uint32_t)rowB & 7u)) << 4);
                ldsm4(bh4[np], kvb + ko);
                ldsm4(bl4[np], kvb + 16384u + ko);
            }
            #pragma unroll
            for (int np = 0; np < 4; ++np){            // hi x hi
                mma_bf16(sacc[2 * np],     ah, bh4[np][0], bh4[np][1]);
                mma_bf16(sacc[2 * np + 1], ah, bh4[np][2], bh4[np][3]);
            }
            #pragma unroll
            for (int np = 0; np < 4; ++np){            // hi x lo
                mma_bf16(sacc[2 * np],     ah, bl4[np][0], bl4[np][1]);
                mma_bf16(sacc[2 * np + 1], ah, bl4[np][2], bl4[np][3]);
            }
            #pragma unroll
            for (int np = 0; np < 4; ++np){            // lo x hi
                mma_bf16(sacc[2 * np],     al, bh4[np][0], bh4[np][1]);
                mma_bf16(sacc[2 * np + 1], al, bh4[np][2], bh4[np][3]);
            }
        }

        // ---- softmax (m=0): p = exp(s+am), causal zeroing; P -> bf16 hi/lo frags ----
        uint32_t PH[8][2], PL[8][2];
        const float* amb = (const float*)(sm + OFF_AMCX + cur * 512);
        const float* cxb = amb + 64;
        float z0 = 0.f, z1 = 0.f;
        #pragma unroll
        for (int j = 0; j < 8; ++j){
            int col = kbase + 8 * j + colt;
            float2 am2 = *(const float2*)&amb[8 * j + colt];
            float2 cx2 = *(const float2*)&cxb[8 * j + colt];
            float p0 = (col     <= qg0) ? __expf(sacc[j][0] + am2.x) : 0.f;
            float p1 = (col + 1 <= qg0) ? __expf(sacc[j][1] + am2.y) : 0.f;
            float p2 = (col     <= qg1) ? __expf(sacc[j][2] + am2.x) : 0.f;
            float p3 = (col + 1 <= qg1) ? __expf(sacc[j][3] + am2.y) : 0.f;
            z0 += p0 + p1;  z1 += p2 + p3;        // Z uses UNSCALED p
            p0 *= cx2.x; p1 *= cx2.y;             // ctx applied post-softmax
            p2 *= cx2.x; p3 *= cx2.y;
            split2(p0, p1, PH[j][0], PL[j][0]);
            split2(p2, p3, PH[j][1], PL[j][1]);
        }
        z0 += __shfl_xor_sync(0xffffffffu, z0, 1);
        z0 += __shfl_xor_sync(0xffffffffu, z0, 2);
        z1 += __shfl_xor_sync(0xffffffffu, z1, 1);
        z1 += __shfl_xor_sync(0xffffffffu, z1, 2);
        z0t += z0;  z1t += z1;

        // ---- O += P V : P from registers, term-major sweeps over 8 accumulators ----
        #pragma unroll
        for (int kb = 0; kb < 4; ++kb){
            uint32_t Ahf[4] = {PH[2 * kb][0], PH[2 * kb][1], PH[2 * kb + 1][0], PH[2 * kb + 1][1]};
            uint32_t Alf[4] = {PL[2 * kb][0], PL[2 * kb][1], PL[2 * kb + 1][0], PL[2 * kb + 1][1]};
            #pragma unroll
            for (int hg = 0; hg < 2; ++hg){
                uint32_t vh[4][4], vl[4][4];
                #pragma unroll
                for (int q = 0; q < 4; ++q){
                    int rowV = 16 * (4 * hg + q) + rB;
                    uint32_t vo = (uint32_t)rowV * 128u
                                + ((((uint32_t)(2 * kb) + cof) ^ ((uint32_t)rowV & 7u)) << 4);
                    ldsm4(vh[q], kvb + 32768u + vo);
                    ldsm4(vl[q], kvb + 49152u + vo);
                }
                #pragma unroll
                for (int q = 0; q < 4; ++q){           // Ph x Vh
                    int np = 4 * hg + q;
                    mma_bf16(oacc[2 * np],     Ahf, vh[q][0], vh[q][1]);
                    mma_bf16(oacc[2 * np + 1], Ahf, vh[q][2], vh[q][3]);
                }
                #pragma unroll
                for (int q = 0; q < 4; ++q){           // Ph x Vl
                    int np = 4 * hg + q;
                    mma_bf16(oacc[2 * np],     Ahf, vl[q][0], vl[q][1]);
                    mma_bf16(oacc[2 * np + 1], Ahf, vl[q][2], vl[q][3]);
                }
                #pragma unroll
                for (int q = 0; q < 4; ++q){           // Pl x Vh
                    int np = 4 * hg + q;
                    mma_bf16(oacc[2 * np],     Alf, vh[q][0], vh[q][1]);
                    mma_bf16(oacc[2 * np + 1], Alf, vh[q][2], vh[q][3]);
                }
            }
        }
    }

    // ---- epilogue: /Z, * head_mask, store ----
    const float hm = HM[h];
    const float i0 = hm / z0t, i1 = hm / z1t;
    float* O0 = out + (((size_t)bh) * SS + q0 + 16 * wid + g) * DD;
    float* O1 = O0 + 8 * DD;
    #pragma unroll
    for (int nb = 0; nb < 16; ++nb){
        *(float2*)&O0[8 * nb + colt] = make_float2(oacc[nb][0] * i0, oacc[nb][1] * i0);
        *(float2*)&O1[8 * nb + colt] = make_float2(oacc[nb][2] * i1, oacc[nb][3] * i1);
    }
}

extern "C" void kernel_launch(void* const* d_in, const int* in_sizes, int n_in,
                              void* d_out, int out_size)
{
    (void)in_sizes; (void)n_in; (void)out_size;
    const float* Q   = (const float*)d_in[0];
    const float* K   = (const float*)d_in[1];
    const float* V   = (const float*)d_in[2];
    const float* AM  = (const float*)d_in[3];
    const float* HM  = (const float*)d_in[4];
    const float* CTX = (const float*)d_in[5];
    float* out = (float*)d_out;

    cudaFuncSetAttribute(attn_hmma_kernel,
                         cudaFuncAttributeMaxDynamicSharedMemorySize, SMEM_TOTAL);

    prep_k_kernel<<<NELEM / 2 / NT, NT>>>(K);
    prep_v_kernel<<<dim3(SS / 32, DD / 32, 2 * HH), NT>>>(V);

    dim3 grid(SS / BM, HH, 2);
    attn_hmma_kernel<<<grid, NT, SMEM_TOTAL>>>(Q, AM, HM, CTX, out);
}